// round 12
// baseline (speedup 1.0000x reference)
#include <cuda_runtime.h>
#include <math.h>

#define N_NODES_MAX 50000
#define N_EDGES_MAX 800000
#define HDIM 64
#define N_GRAPHS 64

// Scratch (device globals — allocation-free, referenced directly in kernels)
__device__ __align__(16) float g_h[N_NODES_MAX * HDIM];     // 12.8 MB
__device__ __align__(16) float g_agg[N_NODES_MAX * HDIM];   // 12.8 MB
__device__ __align__(16) float g_h2[N_NODES_MAX * HDIM];    // 12.8 MB
__device__ __align__(16) float g_gsum[N_GRAPHS * HDIM];
__device__ __align__(16) float g_gcnt[N_GRAPHS];
__device__ __align__(16) int g_deg[N_NODES_MAX + 4];
__device__ __align__(16) int g_rowptr[N_NODES_MAX + 4];
__device__ __align__(16) int g_rank[N_EDGES_MAX + 4];
__device__ __align__(16) int g_col[N_EDGES_MAX];

// ---------------------------------------------------------------------------
// Zeroing: deg only (gates hist) / pool accumulators (off critical path)
// ---------------------------------------------------------------------------
__global__ void zero_deg_kernel(int N) {
    int i = blockIdx.x * blockDim.x + threadIdx.x;
    if (i <= N) g_deg[i] = 0;
}
__global__ void zero_pool_kernel() {
    int i = blockIdx.x * blockDim.x + threadIdx.x;
    if (i < N_GRAPHS * HDIM) g_gsum[i] = 0.f;
    if (i < N_GRAPHS)        g_gcnt[i] = 0.f;
}

// ---------------------------------------------------------------------------
// CSR build: hist captures per-edge rank from the atomic return value,
// so fill is atomic-free.
// ---------------------------------------------------------------------------
__global__ void hist_kernel(const int* __restrict__ ei, int E) {
    int e = (blockIdx.x * blockDim.x + threadIdx.x) * 4;
    if (e + 3 < E) {
        int4 d = *(const int4*)(ei + E + e);
        int4 r;
        r.x = atomicAdd(&g_deg[d.x], 1);
        r.y = atomicAdd(&g_deg[d.y], 1);
        r.z = atomicAdd(&g_deg[d.z], 1);
        r.w = atomicAdd(&g_deg[d.w], 1);
        *(int4*)(g_rank + e) = r;
    } else {
        for (int j = e; j < E; ++j)
            g_rank[j] = atomicAdd(&g_deg[__ldg(&ei[E + j])], 1);
    }
}

// Single-block exclusive scan of g_deg[0..N) -> g_rowptr
__global__ void scan_kernel(int N) {
    __shared__ int wsum[32];
    __shared__ int s_carry;
    int tid = threadIdx.x, lane = tid & 31, wid = tid >> 5;
    if (tid == 0) s_carry = 0;
    __syncthreads();
    const int CHUNK = 4096;
    for (int base = 0; base < N; base += CHUNK) {
        int i0 = base + tid * 4;
        int v0 = 0, v1 = 0, v2 = 0, v3 = 0;
        if (i0 + 3 < N) {
            int4 v = *(const int4*)(g_deg + i0);
            v0 = v.x; v1 = v.y; v2 = v.z; v3 = v.w;
        } else {
            if (i0     < N) v0 = g_deg[i0];
            if (i0 + 1 < N) v1 = g_deg[i0 + 1];
            if (i0 + 2 < N) v2 = g_deg[i0 + 2];
            if (i0 + 3 < N) v3 = g_deg[i0 + 3];
        }
        int tsum = v0 + v1 + v2 + v3;
        int x = tsum;
#pragma unroll
        for (int o = 1; o < 32; o <<= 1) {
            int y = __shfl_up_sync(0xffffffffu, x, o);
            if (lane >= o) x += y;
        }
        if (lane == 31) wsum[wid] = x;
        __syncthreads();
        if (wid == 0) {
            int t = wsum[lane];
#pragma unroll
            for (int o = 1; o < 32; o <<= 1) {
                int y = __shfl_up_sync(0xffffffffu, t, o);
                if (lane >= o) t += y;
            }
            wsum[lane] = t;
        }
        __syncthreads();
        int excl = x - tsum + (wid > 0 ? wsum[wid - 1] : 0) + s_carry;
        if (i0     < N) g_rowptr[i0]     = excl;
        if (i0 + 1 < N) g_rowptr[i0 + 1] = excl + v0;
        if (i0 + 2 < N) g_rowptr[i0 + 2] = excl + v0 + v1;
        if (i0 + 3 < N) g_rowptr[i0 + 3] = excl + v0 + v1 + v2;
        int total = wsum[31];
        __syncthreads();
        if (tid == 0) s_carry += total;
        __syncthreads();
    }
    if (tid == 0) g_rowptr[N] = s_carry;
}

// Atomic-free fill: g_col[rowptr[dst] + rank[e]] = src
__global__ void fill_kernel(const int* __restrict__ ei, int E) {
    int e = (blockIdx.x * blockDim.x + threadIdx.x) * 4;
    if (e + 3 < E) {
        int4 s = *(const int4*)(ei + e);
        int4 d = *(const int4*)(ei + E + e);
        int4 r = *(const int4*)(g_rank + e);
        g_col[__ldg(&g_rowptr[d.x]) + r.x] = s.x;
        g_col[__ldg(&g_rowptr[d.y]) + r.y] = s.y;
        g_col[__ldg(&g_rowptr[d.z]) + r.z] = s.z;
        g_col[__ldg(&g_rowptr[d.w]) + r.w] = s.w;
    } else {
        for (int j = e; j < E; ++j)
            g_col[__ldg(&g_rowptr[__ldg(&ei[E + j])]) + g_rank[j]] = __ldg(&ei[j]);
    }
}

// ---------------------------------------------------------------------------
// Warp-cooperative gather of one node's in-edge sum.
// Half-warp per edge, float4 per lane (2 edges per warp-instruction).
// ---------------------------------------------------------------------------
__device__ __forceinline__ float4 warp_gather_node(
    const float4* __restrict__ hp, int beg, int end,
    int lane, int half, int hl) {
    float4 acc = {0.f, 0.f, 0.f, 0.f};
    int i = beg;
    while (i < end) {
        int m = min(32, end - i);
        int c = (lane < m) ? __ldg(&g_col[i + lane]) : 0;
        int j = 0;
        for (; j + 8 <= m; j += 8) {
            int s0 = __shfl_sync(0xffffffffu, c, j     + half);
            int s1 = __shfl_sync(0xffffffffu, c, j + 2 + half);
            int s2 = __shfl_sync(0xffffffffu, c, j + 4 + half);
            int s3 = __shfl_sync(0xffffffffu, c, j + 6 + half);
            float4 v0 = hp[s0 * 16 + hl];
            float4 v1 = hp[s1 * 16 + hl];
            float4 v2 = hp[s2 * 16 + hl];
            float4 v3 = hp[s3 * 16 + hl];
            acc.x += (v0.x + v1.x) + (v2.x + v3.x);
            acc.y += (v0.y + v1.y) + (v2.y + v3.y);
            acc.z += (v0.z + v1.z) + (v2.z + v3.z);
            acc.w += (v0.w + v1.w) + (v2.w + v3.w);
        }
        for (; j < m; j += 2) {
            int idx = j + half;
            bool valid = idx < m;
            int s = __shfl_sync(0xffffffffu, c, valid ? idx : m - 1);
            float4 v = hp[s * 16 + hl];
            if (valid) {
                acc.x += v.x; acc.y += v.y; acc.z += v.z; acc.w += v.w;
            }
        }
        i += m;
    }
    acc.x += __shfl_xor_sync(0xffffffffu, acc.x, 16);
    acc.y += __shfl_xor_sync(0xffffffffu, acc.y, 16);
    acc.z += __shfl_xor_sync(0xffffffffu, acc.z, 16);
    acc.w += __shfl_xor_sync(0xffffffffu, acc.w, 16);
    return acc;
}

// ---------------------------------------------------------------------------
// Gather over node range [n0, n1): g_agg[n] = relu(gather(g_h, n) + bias)
// ---------------------------------------------------------------------------
__global__ void __launch_bounds__(256, 8)
gather_kernel(const float* __restrict__ bias, int n0, int n1) {
    int w = n0 + ((blockIdx.x * blockDim.x + threadIdx.x) >> 5);
    if (w >= n1) return;
    int lane = threadIdx.x & 31;
    int half = lane >> 4;
    int hl   = lane & 15;
    int beg = __ldg(&g_rowptr[w]);
    int end = __ldg(&g_rowptr[w + 1]);

    float4 acc = warp_gather_node((const float4*)g_h, beg, end, lane, half, hl);

    if (half == 0) {
        float4 b = ((const float4*)bias)[hl];
        float4 o;
        o.x = fmaxf(acc.x + b.x, 0.f);
        o.y = fmaxf(acc.y + b.y, 0.f);
        o.z = fmaxf(acc.z + b.z, 0.f);
        o.w = fmaxf(acc.w + b.w, 0.f);
        ((float4*)g_agg)[w * 16 + hl] = o;
    }
}

// ---------------------------------------------------------------------------
// Gather + mean-pool (layer 2): v = relu(gather(g_h2) + b2); red into gsum.
// ---------------------------------------------------------------------------
__global__ void __launch_bounds__(256, 8)
gather_pool_kernel(const float* __restrict__ b2,
                   const int* __restrict__ batch, int N) {
    int w = (blockIdx.x * blockDim.x + threadIdx.x) >> 5;
    if (w >= N) return;
    int lane = threadIdx.x & 31;
    int half = lane >> 4;
    int hl   = lane & 15;
    int beg = __ldg(&g_rowptr[w]);
    int end = __ldg(&g_rowptr[w + 1]);

    float4 acc = warp_gather_node((const float4*)g_h2, beg, end, lane, half, hl);

    if (half == 0) {
        float4 b = ((const float4*)b2)[hl];
        float4 o;
        o.x = fmaxf(acc.x + b.x, 0.f);
        o.y = fmaxf(acc.y + b.y, 0.f);
        o.z = fmaxf(acc.z + b.z, 0.f);
        o.w = fmaxf(acc.w + b.w, 0.f);
        int g = __ldg(&batch[w]);
        atomicAdd((float4*)(g_gsum + g * HDIM + hl * 4), o);
        if (hl == 0) atomicAdd(&g_gcnt[g], 1.0f);
    }
}

// ---------------------------------------------------------------------------
// Register-tiled GEMM over node range [n0, n1):
//   OUT[n,64] = SRC[n,:K] @ W[K,64]
// ---------------------------------------------------------------------------
template <int K, bool SRC_AGG>
__global__ void gemm_nodes(const float* __restrict__ X,
                           const float* __restrict__ Wg,
                           int n0, int n1) {
    const int KC = 32;
    __shared__ float  xs[128][KC + 1];
    __shared__ float4 ws[KC][16];

    int tid = threadIdx.x;
    int cg  = tid & 15;
    int rt  = tid >> 4;
    int row0 = n0 + blockIdx.x * 128;

    float4 acc[8];
#pragma unroll
    for (int i = 0; i < 8; ++i) acc[i] = make_float4(0.f, 0.f, 0.f, 0.f);

    for (int kc = 0; kc < K; kc += KC) {
#pragma unroll
        for (int j = 0; j < 2; ++j) {
            int id = tid + 256 * j;
            int k = id >> 4, c = id & 15;
            ws[k][c] = ((const float4*)Wg)[(kc + k) * 16 + c];
        }
#pragma unroll
        for (int j = 0; j < 4; ++j) {
            int q = tid + 256 * j;
            int r = q >> 3, c4 = q & 7;
            int row = row0 + r;
            float4 v = make_float4(0.f, 0.f, 0.f, 0.f);
            if (row < n1) {
                const float* srcp = SRC_AGG ? g_agg : X;
                v = *(const float4*)(srcp + row * K + kc + c4 * 4);
            }
            xs[r][c4 * 4]     = v.x;
            xs[r][c4 * 4 + 1] = v.y;
            xs[r][c4 * 4 + 2] = v.z;
            xs[r][c4 * 4 + 3] = v.w;
        }
        __syncthreads();

#pragma unroll
        for (int kk = 0; kk < KC; ++kk) {
            float4 w = ws[kk][cg];
#pragma unroll
            for (int i = 0; i < 8; ++i) {
                float xv = xs[rt * 8 + i][kk];
                acc[i].x += xv * w.x;
                acc[i].y += xv * w.y;
                acc[i].z += xv * w.z;
                acc[i].w += xv * w.w;
            }
        }
        __syncthreads();
    }

    float* outp = SRC_AGG ? g_h2 : g_h;
#pragma unroll
    for (int i = 0; i < 8; ++i) {
        int row = row0 + rt * 8 + i;
        if (row < n1)
            ((float4*)&outp[row * HDIM])[cg] = acc[i];
    }
}

// ---------------------------------------------------------------------------
// Head: pooled -> fc1(relu) -> fc2 -> log_softmax. One thread per graph.
// ---------------------------------------------------------------------------
__global__ void head_kernel(const float* __restrict__ fc1w,
                            const float* __restrict__ fc1b,
                            const float* __restrict__ fc2w,
                            const float* __restrict__ fc2b,
                            float* __restrict__ out) {
    int g = threadIdx.x;
    if (g >= N_GRAPHS) return;

    float inv = 1.0f / fmaxf(g_gcnt[g], 1.0f);
    float p[HDIM];
#pragma unroll
    for (int c = 0; c < HDIM; ++c) p[c] = g_gsum[g * HDIM + c] * inv;

    float z1[32];
#pragma unroll
    for (int j = 0; j < 32; ++j) {
        float s = fc1b[j];
#pragma unroll
        for (int c = 0; c < HDIM; ++c) s += p[c] * fc1w[c * 32 + j];
        z1[j] = fmaxf(s, 0.f);
    }

    float z2[10];
    float m = -1e30f;
#pragma unroll
    for (int k = 0; k < 10; ++k) {
        float s = fc2b[k];
#pragma unroll
        for (int j = 0; j < 32; ++j) s += z1[j] * fc2w[j * 10 + k];
        z2[k] = s;
        m = fmaxf(m, s);
    }
    float se = 0.f;
#pragma unroll
    for (int k = 0; k < 10; ++k) se += expf(z2[k] - m);
    float lse = m + logf(se);
#pragma unroll
    for (int k = 0; k < 10; ++k) out[g * 10 + k] = z2[k] - lse;
}

// ---------------------------------------------------------------------------
// Launch — capturable ops only. Streams/events lazily created OUTSIDE capture.
// Pipeline: build || gemm1, then {gather1+gemm2} split across two streams.
// ---------------------------------------------------------------------------
static cudaStream_t s_side = 0;
static cudaEvent_t  s_ev_fork = 0, s_ev_build = 0, s_ev_gemm1 = 0, s_ev_half1 = 0;

extern "C" void kernel_launch(void* const* d_in, const int* in_sizes, int n_in,
                              void* d_out, int out_size) {
    const float* x     = (const float*)d_in[0];
    const int*   ei    = (const int*)d_in[1];    // int32
    const int*   batch = (const int*)d_in[2];    // int32
    const float* W1    = (const float*)d_in[3];
    const float* b1    = (const float*)d_in[4];
    const float* W2    = (const float*)d_in[5];
    const float* b2    = (const float*)d_in[6];
    const float* fc1w  = (const float*)d_in[7];
    const float* fc1b  = (const float*)d_in[8];
    const float* fc2w  = (const float*)d_in[9];
    const float* fc2b  = (const float*)d_in[10];
    float* out = (float*)d_out;

    int N = in_sizes[0] / 128;   // nodes
    int E = in_sizes[1] / 2;     // edges

    if (!s_side) {
        cudaStreamCreateWithFlags(&s_side, cudaStreamNonBlocking);
        cudaEventCreateWithFlags(&s_ev_fork,  cudaEventDisableTiming);
        cudaEventCreateWithFlags(&s_ev_build, cudaEventDisableTiming);
        cudaEventCreateWithFlags(&s_ev_gemm1, cudaEventDisableTiming);
        cudaEventCreateWithFlags(&s_ev_half1, cudaEventDisableTiming);
    }

    int NH = (N + 255) & ~255;   // half boundary, multiple of 256
    NH = NH / 2;
    NH = (NH + 127) & ~127;      // keep 128-aligned for gemm tiles
    if (NH > N) NH = N;

    int edge4_blocks = (E / 4 + 255) / 256 + 1;

    // Fork: CSR build + pool zero on side stream
    cudaEventRecord(s_ev_fork, 0);
    cudaStreamWaitEvent(s_side, s_ev_fork, 0);

    zero_deg_kernel<<<(N + 256) / 256, 256, 0, s_side>>>(N);
    hist_kernel<<<edge4_blocks, 256, 0, s_side>>>(ei, E);
    scan_kernel<<<1, 1024, 0, s_side>>>(N);
    fill_kernel<<<edge4_blocks, 256, 0, s_side>>>(ei, E);
    zero_pool_kernel<<<(N_GRAPHS * HDIM + 255) / 256, 256, 0, s_side>>>();
    cudaEventRecord(s_ev_build, s_side);

    // Main: gemm1 overlaps the build
    gemm_nodes<128, false><<<(N + 127) / 128, 256>>>(x, W1, 0, N);
    cudaEventRecord(s_ev_gemm1, 0);

    // Pipeline: half0 on main, half1 on side (both need build + gemm1)
    cudaStreamWaitEvent(0, s_ev_build, 0);
    cudaStreamWaitEvent(s_side, s_ev_gemm1, 0);

    int h0_nodes = NH, h1_nodes = N - NH;

    gather_kernel<<<(h0_nodes * 32 + 255) / 256, 256>>>(b1, 0, NH);
    gemm_nodes<64, true><<<(h0_nodes + 127) / 128, 256>>>(x, W2, 0, NH);

    if (h1_nodes > 0) {
        gather_kernel<<<(h1_nodes * 32 + 255) / 256, 256, 0, s_side>>>(b1, NH, N);
        gemm_nodes<64, true><<<(h1_nodes + 127) / 128, 256, 0, s_side>>>(x, W2, NH, N);
    }
    cudaEventRecord(s_ev_half1, s_side);
    cudaStreamWaitEvent(0, s_ev_half1, 0);

    // Layer-2 aggregate + pool (needs all of g_h2)
    gather_pool_kernel<<<(N * 32 + 255) / 256, 256>>>(b2, batch, N);

    // Head
    head_kernel<<<1, 64>>>(fc1w, fc1b, fc2w, fc2b, out);
}

// round 13
// speedup vs baseline: 1.3995x; 1.3995x over previous
#include <cuda_runtime.h>
#include <math.h>

#define N_NODES_MAX 50000
#define N_EDGES_MAX 800000
#define HDIM 64
#define N_GRAPHS 64

// Scratch (device globals — allocation-free, referenced directly in kernels)
__device__ __align__(16) float g_h[N_NODES_MAX * HDIM];     // 12.8 MB
__device__ __align__(16) float g_agg[N_NODES_MAX * HDIM];   // 12.8 MB
__device__ __align__(16) float g_gsum[N_GRAPHS * HDIM];
__device__ __align__(16) float g_gcnt[N_GRAPHS];
__device__ __align__(16) int g_deg[N_NODES_MAX + 4];
__device__ __align__(16) int g_rowptr[N_NODES_MAX + 4];
__device__ __align__(16) int g_rank[N_EDGES_MAX + 4];
__device__ __align__(16) int g_col[N_EDGES_MAX];

// ---------------------------------------------------------------------------
// Zero degree histogram + pool accumulators
// ---------------------------------------------------------------------------
__global__ void zero_small_kernel(int N) {
    int i = blockIdx.x * blockDim.x + threadIdx.x;
    if (i <= N)               g_deg[i]  = 0;
    if (i < N_GRAPHS * HDIM)  g_gsum[i] = 0.f;
    if (i < N_GRAPHS)         g_gcnt[i] = 0.f;
}

// ---------------------------------------------------------------------------
// CSR build: hist captures per-edge rank from the atomic return value,
// so fill is atomic-free.
// ---------------------------------------------------------------------------
__global__ void hist_kernel(const int* __restrict__ ei, int E) {
    int e = (blockIdx.x * blockDim.x + threadIdx.x) * 4;
    if (e + 3 < E) {
        int4 d = *(const int4*)(ei + E + e);
        int4 r;
        r.x = atomicAdd(&g_deg[d.x], 1);
        r.y = atomicAdd(&g_deg[d.y], 1);
        r.z = atomicAdd(&g_deg[d.z], 1);
        r.w = atomicAdd(&g_deg[d.w], 1);
        *(int4*)(g_rank + e) = r;
    } else {
        for (int j = e; j < E; ++j)
            g_rank[j] = atomicAdd(&g_deg[__ldg(&ei[E + j])], 1);
    }
}

// Single-block exclusive scan of g_deg[0..N) -> g_rowptr
__global__ void scan_kernel(int N) {
    __shared__ int wsum[32];
    __shared__ int s_carry;
    int tid = threadIdx.x, lane = tid & 31, wid = tid >> 5;
    if (tid == 0) s_carry = 0;
    __syncthreads();
    const int CHUNK = 4096;
    for (int base = 0; base < N; base += CHUNK) {
        int i0 = base + tid * 4;
        int v0 = 0, v1 = 0, v2 = 0, v3 = 0;
        if (i0 + 3 < N) {
            int4 v = *(const int4*)(g_deg + i0);
            v0 = v.x; v1 = v.y; v2 = v.z; v3 = v.w;
        } else {
            if (i0     < N) v0 = g_deg[i0];
            if (i0 + 1 < N) v1 = g_deg[i0 + 1];
            if (i0 + 2 < N) v2 = g_deg[i0 + 2];
            if (i0 + 3 < N) v3 = g_deg[i0 + 3];
        }
        int tsum = v0 + v1 + v2 + v3;
        int x = tsum;
#pragma unroll
        for (int o = 1; o < 32; o <<= 1) {
            int y = __shfl_up_sync(0xffffffffu, x, o);
            if (lane >= o) x += y;
        }
        if (lane == 31) wsum[wid] = x;
        __syncthreads();
        if (wid == 0) {
            int t = wsum[lane];
#pragma unroll
            for (int o = 1; o < 32; o <<= 1) {
                int y = __shfl_up_sync(0xffffffffu, t, o);
                if (lane >= o) t += y;
            }
            wsum[lane] = t;
        }
        __syncthreads();
        int excl = x - tsum + (wid > 0 ? wsum[wid - 1] : 0) + s_carry;
        if (i0     < N) g_rowptr[i0]     = excl;
        if (i0 + 1 < N) g_rowptr[i0 + 1] = excl + v0;
        if (i0 + 2 < N) g_rowptr[i0 + 2] = excl + v0 + v1;
        if (i0 + 3 < N) g_rowptr[i0 + 3] = excl + v0 + v1 + v2;
        int total = wsum[31];
        __syncthreads();
        if (tid == 0) s_carry += total;
        __syncthreads();
    }
    if (tid == 0) g_rowptr[N] = s_carry;
}

// Atomic-free fill: g_col[rowptr[dst] + rank[e]] = src
__global__ void fill_kernel(const int* __restrict__ ei, int E) {
    int e = (blockIdx.x * blockDim.x + threadIdx.x) * 4;
    if (e + 3 < E) {
        int4 s = *(const int4*)(ei + e);
        int4 d = *(const int4*)(ei + E + e);
        int4 r = *(const int4*)(g_rank + e);
        g_col[__ldg(&g_rowptr[d.x]) + r.x] = s.x;
        g_col[__ldg(&g_rowptr[d.y]) + r.y] = s.y;
        g_col[__ldg(&g_rowptr[d.z]) + r.z] = s.z;
        g_col[__ldg(&g_rowptr[d.w]) + r.w] = s.w;
    } else {
        for (int j = e; j < E; ++j)
            g_col[__ldg(&g_rowptr[__ldg(&ei[E + j])]) + g_rank[j]] = __ldg(&ei[j]);
    }
}

// ---------------------------------------------------------------------------
// Warp-cooperative gather of one node's in-edge sum.
// Half-warp per edge, float4 per lane.  16-edge main batch = 8 LDG.128 in
// flight per lane (MLP=8) matching the mean degree of 16.
// ---------------------------------------------------------------------------
__device__ __forceinline__ float4 warp_gather_node(
    const float4* __restrict__ hp, int beg, int end,
    int lane, int half, int hl) {
    float4 acc = {0.f, 0.f, 0.f, 0.f};
    int i = beg;
    while (i < end) {
        int m = min(32, end - i);
        int c = (lane < m) ? __ldg(&g_col[i + lane]) : 0;
        int j = 0;
        for (; j + 16 <= m; j += 16) {     // 16 edges: 8 pair-steps in flight
            int s[8];
            float4 v[8];
#pragma unroll
            for (int q = 0; q < 8; ++q)
                s[q] = __shfl_sync(0xffffffffu, c, j + 2 * q + half);
#pragma unroll
            for (int q = 0; q < 8; ++q)
                v[q] = hp[s[q] * 16 + hl];
#pragma unroll
            for (int q = 0; q < 8; ++q) {
                acc.x += v[q].x;
                acc.y += v[q].y;
                acc.z += v[q].z;
                acc.w += v[q].w;
            }
        }
        for (; j + 8 <= m; j += 8) {       // 8-edge batch
            int s0 = __shfl_sync(0xffffffffu, c, j     + half);
            int s1 = __shfl_sync(0xffffffffu, c, j + 2 + half);
            int s2 = __shfl_sync(0xffffffffu, c, j + 4 + half);
            int s3 = __shfl_sync(0xffffffffu, c, j + 6 + half);
            float4 v0 = hp[s0 * 16 + hl];
            float4 v1 = hp[s1 * 16 + hl];
            float4 v2 = hp[s2 * 16 + hl];
            float4 v3 = hp[s3 * 16 + hl];
            acc.x += (v0.x + v1.x) + (v2.x + v3.x);
            acc.y += (v0.y + v1.y) + (v2.y + v3.y);
            acc.z += (v0.z + v1.z) + (v2.z + v3.z);
            acc.w += (v0.w + v1.w) + (v2.w + v3.w);
        }
        for (; j < m; j += 2) {            // tail pairs
            int idx = j + half;
            bool valid = idx < m;
            int s = __shfl_sync(0xffffffffu, c, valid ? idx : m - 1);
            float4 v = hp[s * 16 + hl];
            if (valid) {
                acc.x += v.x; acc.y += v.y; acc.z += v.z; acc.w += v.w;
            }
        }
        i += m;
    }
    acc.x += __shfl_xor_sync(0xffffffffu, acc.x, 16);
    acc.y += __shfl_xor_sync(0xffffffffu, acc.y, 16);
    acc.z += __shfl_xor_sync(0xffffffffu, acc.z, 16);
    acc.w += __shfl_xor_sync(0xffffffffu, acc.w, 16);
    return acc;
}

// ---------------------------------------------------------------------------
// Layer-1 aggregate: g_agg[n] = relu(gather(g_h, n) + b1)
// ---------------------------------------------------------------------------
__global__ void __launch_bounds__(256, 8)
gather_kernel(const float* __restrict__ bias, int N) {
    int w = (blockIdx.x * blockDim.x + threadIdx.x) >> 5;
    if (w >= N) return;
    int lane = threadIdx.x & 31;
    int half = lane >> 4;
    int hl   = lane & 15;
    int beg = __ldg(&g_rowptr[w]);
    int end = __ldg(&g_rowptr[w + 1]);

    float4 acc = warp_gather_node((const float4*)g_h, beg, end, lane, half, hl);

    if (half == 0) {
        float4 b = ((const float4*)bias)[hl];
        float4 o;
        o.x = fmaxf(acc.x + b.x, 0.f);
        o.y = fmaxf(acc.y + b.y, 0.f);
        o.z = fmaxf(acc.z + b.z, 0.f);
        o.w = fmaxf(acc.w + b.w, 0.f);
        ((float4*)g_agg)[w * 16 + hl] = o;
    }
}

// ---------------------------------------------------------------------------
// Layer-2 aggregate + mean-pool: v = relu(gather(g_h)+b2); pool into gsum.
// batch is SORTED, so the 8 nodes of a block are nearly always one graph:
// reduce across the block in smem and emit ONE set of atomics per block.
// Mixed-graph / partial blocks fall back to per-node atomics.
// ---------------------------------------------------------------------------
__global__ void __launch_bounds__(256, 8)
gather_pool_kernel(const float* __restrict__ b2,
                   const int* __restrict__ batch, int N) {
    __shared__ float4 red[8][16];
    __shared__ int    sg[8];

    int wid  = threadIdx.x >> 5;
    int lane = threadIdx.x & 31;
    int half = lane >> 4;
    int hl   = lane & 15;
    int w = blockIdx.x * 8 + wid;
    bool active = w < N;

    float4 o = {0.f, 0.f, 0.f, 0.f};
    int g = -1;
    if (active) {
        int beg = __ldg(&g_rowptr[w]);
        int end = __ldg(&g_rowptr[w + 1]);
        float4 acc = warp_gather_node((const float4*)g_h, beg, end, lane, half, hl);
        if (half == 0) {
            float4 b = ((const float4*)b2)[hl];
            o.x = fmaxf(acc.x + b.x, 0.f);
            o.y = fmaxf(acc.y + b.y, 0.f);
            o.z = fmaxf(acc.z + b.z, 0.f);
            o.w = fmaxf(acc.w + b.w, 0.f);
        }
        g = __ldg(&batch[w]);
    }
    if (half == 0) red[wid][hl] = o;
    if (lane == 0) sg[wid] = g;
    __syncthreads();

    int g0 = sg[0];
    bool uniform = (g0 >= 0);
#pragma unroll
    for (int q = 1; q < 8; ++q) uniform = uniform && (sg[q] == g0);

    if (uniform) {
        if (wid == 0 && half == 0) {
            float4 s = red[0][hl];
#pragma unroll
            for (int q = 1; q < 8; ++q) {
                s.x += red[q][hl].x;
                s.y += red[q][hl].y;
                s.z += red[q][hl].z;
                s.w += red[q][hl].w;
            }
            atomicAdd((float4*)(g_gsum + g0 * HDIM + hl * 4), s);
            if (hl == 0) atomicAdd(&g_gcnt[g0], 8.0f);
        }
    } else {
        if (active && half == 0) {
            atomicAdd((float4*)(g_gsum + g * HDIM + hl * 4), o);
            if (hl == 0) atomicAdd(&g_gcnt[g], 1.0f);
        }
    }
}

// ---------------------------------------------------------------------------
// Register-tiled GEMM: g_h[n,64] = src(n,:K) @ W[K,64]
// (layer2 reads g_agg and overwrites g_h — layer-1 h no longer needed)
// ---------------------------------------------------------------------------
template <int K, bool SRC_AGG>
__global__ void gemm_nodes(const float* __restrict__ X,
                           const float* __restrict__ Wg,
                           int N) {
    const int KC = 32;
    __shared__ float  xs[128][KC + 1];
    __shared__ float4 ws[KC][16];

    int tid = threadIdx.x;
    int cg  = tid & 15;
    int rt  = tid >> 4;
    int row0 = blockIdx.x * 128;

    float4 acc[8];
#pragma unroll
    for (int i = 0; i < 8; ++i) acc[i] = make_float4(0.f, 0.f, 0.f, 0.f);

    for (int kc = 0; kc < K; kc += KC) {
#pragma unroll
        for (int j = 0; j < 2; ++j) {
            int id = tid + 256 * j;
            int k = id >> 4, c = id & 15;
            ws[k][c] = ((const float4*)Wg)[(kc + k) * 16 + c];
        }
#pragma unroll
        for (int j = 0; j < 4; ++j) {
            int q = tid + 256 * j;
            int r = q >> 3, c4 = q & 7;
            int row = row0 + r;
            float4 v = make_float4(0.f, 0.f, 0.f, 0.f);
            if (row < N) {
                const float* srcp = SRC_AGG ? g_agg : X;
                v = *(const float4*)(srcp + row * K + kc + c4 * 4);
            }
            xs[r][c4 * 4]     = v.x;
            xs[r][c4 * 4 + 1] = v.y;
            xs[r][c4 * 4 + 2] = v.z;
            xs[r][c4 * 4 + 3] = v.w;
        }
        __syncthreads();

#pragma unroll
        for (int kk = 0; kk < KC; ++kk) {
            float4 w = ws[kk][cg];
#pragma unroll
            for (int i = 0; i < 8; ++i) {
                float xv = xs[rt * 8 + i][kk];
                acc[i].x += xv * w.x;
                acc[i].y += xv * w.y;
                acc[i].z += xv * w.z;
                acc[i].w += xv * w.w;
            }
        }
        __syncthreads();
    }

#pragma unroll
    for (int i = 0; i < 8; ++i) {
        int row = row0 + rt * 8 + i;
        if (row < N)
            ((float4*)&g_h[row * HDIM])[cg] = acc[i];
    }
}

// ---------------------------------------------------------------------------
// Head: pooled -> fc1(relu) -> fc2 -> log_softmax. One thread per graph.
// ---------------------------------------------------------------------------
__global__ void head_kernel(const float* __restrict__ fc1w,
                            const float* __restrict__ fc1b,
                            const float* __restrict__ fc2w,
                            const float* __restrict__ fc2b,
                            float* __restrict__ out) {
    int g = threadIdx.x;
    if (g >= N_GRAPHS) return;

    float inv = 1.0f / fmaxf(g_gcnt[g], 1.0f);
    float p[HDIM];
#pragma unroll
    for (int c = 0; c < HDIM; ++c) p[c] = g_gsum[g * HDIM + c] * inv;

    float z1[32];
#pragma unroll
    for (int j = 0; j < 32; ++j) {
        float s = fc1b[j];
#pragma unroll
        for (int c = 0; c < HDIM; ++c) s += p[c] * fc1w[c * 32 + j];
        z1[j] = fmaxf(s, 0.f);
    }

    float z2[10];
    float m = -1e30f;
#pragma unroll
    for (int k = 0; k < 10; ++k) {
        float s = fc2b[k];
#pragma unroll
        for (int j = 0; j < 32; ++j) s += z1[j] * fc2w[j * 10 + k];
        z2[k] = s;
        m = fmaxf(m, s);
    }
    float se = 0.f;
#pragma unroll
    for (int k = 0; k < 10; ++k) se += expf(z2[k] - m);
    float lse = m + logf(se);
#pragma unroll
    for (int k = 0; k < 10; ++k) out[g * 10 + k] = z2[k] - lse;
}

// ---------------------------------------------------------------------------
// Launch — round-10 topology (proven): build || gemm1, then serial.
// Streams/events lazily created OUTSIDE capture.
// ---------------------------------------------------------------------------
static cudaStream_t s_side = 0;
static cudaEvent_t  s_ev_fork = 0, s_ev_join = 0;

extern "C" void kernel_launch(void* const* d_in, const int* in_sizes, int n_in,
                              void* d_out, int out_size) {
    const float* x     = (const float*)d_in[0];
    const int*   ei    = (const int*)d_in[1];    // int32
    const int*   batch = (const int*)d_in[2];    // int32
    const float* W1    = (const float*)d_in[3];
    const float* b1    = (const float*)d_in[4];
    const float* W2    = (const float*)d_in[5];
    const float* b2    = (const float*)d_in[6];
    const float* fc1w  = (const float*)d_in[7];
    const float* fc1b  = (const float*)d_in[8];
    const float* fc2w  = (const float*)d_in[9];
    const float* fc2b  = (const float*)d_in[10];
    float* out = (float*)d_out;

    int N = in_sizes[0] / 128;   // nodes
    int E = in_sizes[1] / 2;     // edges

    if (!s_side) {
        cudaStreamCreateWithFlags(&s_side, cudaStreamNonBlocking);
        cudaEventCreateWithFlags(&s_ev_fork, cudaEventDisableTiming);
        cudaEventCreateWithFlags(&s_ev_join, cudaEventDisableTiming);
    }

    int gemm_blocks   = (N + 127) / 128;
    int edge4_blocks  = (E / 4 + 255) / 256 + 1;
    int gather_blocks = (N * 32 + 255) / 256;
    int pool_blocks   = (N + 7) / 8;

    // Fork: CSR build on side stream, concurrent with gemm1 on main stream
    cudaEventRecord(s_ev_fork, 0);
    cudaStreamWaitEvent(s_side, s_ev_fork, 0);

    zero_small_kernel<<<(N + 256) / 256, 256, 0, s_side>>>(N);
    hist_kernel<<<edge4_blocks, 256, 0, s_side>>>(ei, E);
    scan_kernel<<<1, 1024, 0, s_side>>>(N);
    fill_kernel<<<edge4_blocks, 256, 0, s_side>>>(ei, E);
    cudaEventRecord(s_ev_join, s_side);

    // Main stream: gemm1 overlaps the build
    gemm_nodes<128, false><<<gemm_blocks, 256>>>(x, W1, N);

    // Join: gather needs both g_h and the CSR
    cudaStreamWaitEvent(0, s_ev_join, 0);

    // Layer 1 aggregate: g_agg = relu(gather(g_h) + b1)
    gather_kernel<<<gather_blocks, 256>>>(b1, N);

    // Layer 2: g_h = g_agg @ W2 ; pool-fused gather with b2
    gemm_nodes<64, true><<<gemm_blocks, 256>>>(x, W2, N);
    gather_pool_kernel<<<pool_blocks, 256>>>(b2, batch, N);

    // Head
    head_kernel<<<1, 64>>>(fc1w, fc1b, fc2w, fc2b, out);
}

// round 14
// speedup vs baseline: 1.4316x; 1.0229x over previous
#include <cuda_runtime.h>
#include <cuda_fp16.h>
#include <math.h>

#define N_NODES_MAX 50000
#define N_EDGES_MAX 800000
#define HDIM 64
#define N_GRAPHS 64

// Scratch (device globals — allocation-free, referenced directly in kernels)
__device__ __align__(128) __half g_hh[N_NODES_MAX * HDIM];   // 6.4 MB (fp16 h)
__device__ __align__(16) float g_agg[N_NODES_MAX * HDIM];    // 12.8 MB
__device__ __align__(16) float g_gsum[N_GRAPHS * HDIM];
__device__ __align__(16) float g_gcnt[N_GRAPHS];
__device__ __align__(16) int g_deg[N_NODES_MAX + 4];
__device__ __align__(16) int g_rowptr[N_NODES_MAX + 4];
__device__ __align__(16) int g_rank[N_EDGES_MAX + 4];
__device__ __align__(16) int g_col[N_EDGES_MAX];

struct __align__(8) H4 { __half2 a, b; };

// ---------------------------------------------------------------------------
// Zero degree histogram + pool accumulators
// ---------------------------------------------------------------------------
__global__ void zero_small_kernel(int N) {
    int i = blockIdx.x * blockDim.x + threadIdx.x;
    if (i <= N)               g_deg[i]  = 0;
    if (i < N_GRAPHS * HDIM)  g_gsum[i] = 0.f;
    if (i < N_GRAPHS)         g_gcnt[i] = 0.f;
}

// ---------------------------------------------------------------------------
// CSR build: hist captures per-edge rank from the atomic return value,
// so fill is atomic-free.
// ---------------------------------------------------------------------------
__global__ void hist_kernel(const int* __restrict__ ei, int E) {
    int e = (blockIdx.x * blockDim.x + threadIdx.x) * 4;
    if (e + 3 < E) {
        int4 d = *(const int4*)(ei + E + e);
        int4 r;
        r.x = atomicAdd(&g_deg[d.x], 1);
        r.y = atomicAdd(&g_deg[d.y], 1);
        r.z = atomicAdd(&g_deg[d.z], 1);
        r.w = atomicAdd(&g_deg[d.w], 1);
        *(int4*)(g_rank + e) = r;
    } else {
        for (int j = e; j < E; ++j)
            g_rank[j] = atomicAdd(&g_deg[__ldg(&ei[E + j])], 1);
    }
}

// Single-block exclusive scan of g_deg[0..N) -> g_rowptr
__global__ void scan_kernel(int N) {
    __shared__ int wsum[32];
    __shared__ int s_carry;
    int tid = threadIdx.x, lane = tid & 31, wid = tid >> 5;
    if (tid == 0) s_carry = 0;
    __syncthreads();
    const int CHUNK = 4096;
    for (int base = 0; base < N; base += CHUNK) {
        int i0 = base + tid * 4;
        int v0 = 0, v1 = 0, v2 = 0, v3 = 0;
        if (i0 + 3 < N) {
            int4 v = *(const int4*)(g_deg + i0);
            v0 = v.x; v1 = v.y; v2 = v.z; v3 = v.w;
        } else {
            if (i0     < N) v0 = g_deg[i0];
            if (i0 + 1 < N) v1 = g_deg[i0 + 1];
            if (i0 + 2 < N) v2 = g_deg[i0 + 2];
            if (i0 + 3 < N) v3 = g_deg[i0 + 3];
        }
        int tsum = v0 + v1 + v2 + v3;
        int x = tsum;
#pragma unroll
        for (int o = 1; o < 32; o <<= 1) {
            int y = __shfl_up_sync(0xffffffffu, x, o);
            if (lane >= o) x += y;
        }
        if (lane == 31) wsum[wid] = x;
        __syncthreads();
        if (wid == 0) {
            int t = wsum[lane];
#pragma unroll
            for (int o = 1; o < 32; o <<= 1) {
                int y = __shfl_up_sync(0xffffffffu, t, o);
                if (lane >= o) t += y;
            }
            wsum[lane] = t;
        }
        __syncthreads();
        int excl = x - tsum + (wid > 0 ? wsum[wid - 1] : 0) + s_carry;
        if (i0     < N) g_rowptr[i0]     = excl;
        if (i0 + 1 < N) g_rowptr[i0 + 1] = excl + v0;
        if (i0 + 2 < N) g_rowptr[i0 + 2] = excl + v0 + v1;
        if (i0 + 3 < N) g_rowptr[i0 + 3] = excl + v0 + v1 + v2;
        int total = wsum[31];
        __syncthreads();
        if (tid == 0) s_carry += total;
        __syncthreads();
    }
    if (tid == 0) g_rowptr[N] = s_carry;
}

// Atomic-free fill: g_col[rowptr[dst] + rank[e]] = src
__global__ void fill_kernel(const int* __restrict__ ei, int E) {
    int e = (blockIdx.x * blockDim.x + threadIdx.x) * 4;
    if (e + 3 < E) {
        int4 s = *(const int4*)(ei + e);
        int4 d = *(const int4*)(ei + E + e);
        int4 r = *(const int4*)(g_rank + e);
        g_col[__ldg(&g_rowptr[d.x]) + r.x] = s.x;
        g_col[__ldg(&g_rowptr[d.y]) + r.y] = s.y;
        g_col[__ldg(&g_rowptr[d.z]) + r.z] = s.z;
        g_col[__ldg(&g_rowptr[d.w]) + r.w] = s.w;
    } else {
        for (int j = e; j < E; ++j)
            g_col[__ldg(&g_rowptr[__ldg(&ei[E + j])]) + g_rank[j]] = __ldg(&ei[j]);
    }
}

// ---------------------------------------------------------------------------
// Warp-cooperative gather from the fp16 h buffer.
// Row = 64 halves = 128B = 16 uint2; half-warp per edge, uint2 (4 cols) per
// lane -> ONE 128B line per edge per half-warp.  fp32 accumulation.
// ---------------------------------------------------------------------------
__device__ __forceinline__ void h4_add(float4& acc, uint2 u) {
    __half2 p0 = *(__half2*)&u.x;
    __half2 p1 = *(__half2*)&u.y;
    float2 f0 = __half22float2(p0);
    float2 f1 = __half22float2(p1);
    acc.x += f0.x; acc.y += f0.y; acc.z += f1.x; acc.w += f1.y;
}

__device__ __forceinline__ float4 warp_gather_node(
    int beg, int end, int lane, int half, int hl) {
    const uint2* hp = (const uint2*)g_hh;   // 16 uint2 per row
    float4 acc = {0.f, 0.f, 0.f, 0.f};
    int i = beg;
    while (i < end) {
        int m = min(32, end - i);
        int c = (lane < m) ? __ldg(&g_col[i + lane]) : 0;
        int j = 0;
        for (; j + 16 <= m; j += 16) {     // 16 edges: 8 loads in flight/lane
            int s[8];
            uint2 v[8];
#pragma unroll
            for (int q = 0; q < 8; ++q)
                s[q] = __shfl_sync(0xffffffffu, c, j + 2 * q + half);
#pragma unroll
            for (int q = 0; q < 8; ++q)
                v[q] = hp[s[q] * 16 + hl];
#pragma unroll
            for (int q = 0; q < 8; ++q)
                h4_add(acc, v[q]);
        }
        for (; j + 8 <= m; j += 8) {
            int s0 = __shfl_sync(0xffffffffu, c, j     + half);
            int s1 = __shfl_sync(0xffffffffu, c, j + 2 + half);
            int s2 = __shfl_sync(0xffffffffu, c, j + 4 + half);
            int s3 = __shfl_sync(0xffffffffu, c, j + 6 + half);
            uint2 v0 = hp[s0 * 16 + hl];
            uint2 v1 = hp[s1 * 16 + hl];
            uint2 v2 = hp[s2 * 16 + hl];
            uint2 v3 = hp[s3 * 16 + hl];
            h4_add(acc, v0); h4_add(acc, v1);
            h4_add(acc, v2); h4_add(acc, v3);
        }
        for (; j < m; j += 2) {
            int idx = j + half;
            bool valid = idx < m;
            int s = __shfl_sync(0xffffffffu, c, valid ? idx : m - 1);
            uint2 v = hp[s * 16 + hl];
            if (valid) h4_add(acc, v);
        }
        i += m;
    }
    acc.x += __shfl_xor_sync(0xffffffffu, acc.x, 16);
    acc.y += __shfl_xor_sync(0xffffffffu, acc.y, 16);
    acc.z += __shfl_xor_sync(0xffffffffu, acc.z, 16);
    acc.w += __shfl_xor_sync(0xffffffffu, acc.w, 16);
    return acc;
}

// ---------------------------------------------------------------------------
// Layer-1 aggregate: g_agg[n] = relu(gather(g_hh, n) + b1)   (fp32 out)
// Each lane's float4 covers cols [hl*4, hl*4+3] — same as uint2 cols.
// ---------------------------------------------------------------------------
__global__ void __launch_bounds__(256, 8)
gather_kernel(const float* __restrict__ bias, int N) {
    int w = (blockIdx.x * blockDim.x + threadIdx.x) >> 5;
    if (w >= N) return;
    int lane = threadIdx.x & 31;
    int half = lane >> 4;
    int hl   = lane & 15;
    int beg = __ldg(&g_rowptr[w]);
    int end = __ldg(&g_rowptr[w + 1]);

    float4 acc = warp_gather_node(beg, end, lane, half, hl);

    if (half == 0) {
        float4 b = ((const float4*)bias)[hl];
        float4 o;
        o.x = fmaxf(acc.x + b.x, 0.f);
        o.y = fmaxf(acc.y + b.y, 0.f);
        o.z = fmaxf(acc.z + b.z, 0.f);
        o.w = fmaxf(acc.w + b.w, 0.f);
        ((float4*)g_agg)[w * 16 + hl] = o;
    }
}

// ---------------------------------------------------------------------------
// Layer-2 aggregate + mean-pool: v = relu(gather(g_hh)+b2); pool into gsum.
// Sorted batch -> block-level reduction, one atomic set per uniform block.
// ---------------------------------------------------------------------------
__global__ void __launch_bounds__(256, 8)
gather_pool_kernel(const float* __restrict__ b2,
                   const int* __restrict__ batch, int N) {
    __shared__ float4 red[8][16];
    __shared__ int    sg[8];

    int wid  = threadIdx.x >> 5;
    int lane = threadIdx.x & 31;
    int half = lane >> 4;
    int hl   = lane & 15;
    int w = blockIdx.x * 8 + wid;
    bool active = w < N;

    float4 o = {0.f, 0.f, 0.f, 0.f};
    int g = -1;
    if (active) {
        int beg = __ldg(&g_rowptr[w]);
        int end = __ldg(&g_rowptr[w + 1]);
        float4 acc = warp_gather_node(beg, end, lane, half, hl);
        if (half == 0) {
            float4 b = ((const float4*)b2)[hl];
            o.x = fmaxf(acc.x + b.x, 0.f);
            o.y = fmaxf(acc.y + b.y, 0.f);
            o.z = fmaxf(acc.z + b.z, 0.f);
            o.w = fmaxf(acc.w + b.w, 0.f);
        }
        g = __ldg(&batch[w]);
    }
    if (half == 0) red[wid][hl] = o;
    if (lane == 0) sg[wid] = g;
    __syncthreads();

    int g0 = sg[0];
    bool uniform = (g0 >= 0);
#pragma unroll
    for (int q = 1; q < 8; ++q) uniform = uniform && (sg[q] == g0);

    if (uniform) {
        if (wid == 0 && half == 0) {
            float4 s = red[0][hl];
#pragma unroll
            for (int q = 1; q < 8; ++q) {
                s.x += red[q][hl].x;
                s.y += red[q][hl].y;
                s.z += red[q][hl].z;
                s.w += red[q][hl].w;
            }
            atomicAdd((float4*)(g_gsum + g0 * HDIM + hl * 4), s);
            if (hl == 0) atomicAdd(&g_gcnt[g0], 8.0f);
        }
    } else {
        if (active && half == 0) {
            atomicAdd((float4*)(g_gsum + g * HDIM + hl * 4), o);
            if (hl == 0) atomicAdd(&g_gcnt[g], 1.0f);
        }
    }
}

// ---------------------------------------------------------------------------
// Register-tiled GEMM: g_hh[n,64] = (fp16) src(n,:K) @ W[K,64]
// fp32 smem staging + fp32 accumulate; epilogue converts to half2 pairs.
// ---------------------------------------------------------------------------
template <int K, bool SRC_AGG>
__global__ void gemm_nodes(const float* __restrict__ X,
                           const float* __restrict__ Wg,
                           int N) {
    const int KC = 32;
    __shared__ float  xs[128][KC + 1];
    __shared__ float4 ws[KC][16];

    int tid = threadIdx.x;
    int cg  = tid & 15;
    int rt  = tid >> 4;
    int row0 = blockIdx.x * 128;

    float4 acc[8];
#pragma unroll
    for (int i = 0; i < 8; ++i) acc[i] = make_float4(0.f, 0.f, 0.f, 0.f);

    for (int kc = 0; kc < K; kc += KC) {
#pragma unroll
        for (int j = 0; j < 2; ++j) {
            int id = tid + 256 * j;
            int k = id >> 4, c = id & 15;
            ws[k][c] = ((const float4*)Wg)[(kc + k) * 16 + c];
        }
#pragma unroll
        for (int j = 0; j < 4; ++j) {
            int q = tid + 256 * j;
            int r = q >> 3, c4 = q & 7;
            int row = row0 + r;
            float4 v = make_float4(0.f, 0.f, 0.f, 0.f);
            if (row < N) {
                const float* srcp = SRC_AGG ? g_agg : X;
                v = *(const float4*)(srcp + row * K + kc + c4 * 4);
            }
            xs[r][c4 * 4]     = v.x;
            xs[r][c4 * 4 + 1] = v.y;
            xs[r][c4 * 4 + 2] = v.z;
            xs[r][c4 * 4 + 3] = v.w;
        }
        __syncthreads();

#pragma unroll
        for (int kk = 0; kk < KC; ++kk) {
            float4 w = ws[kk][cg];
#pragma unroll
            for (int i = 0; i < 8; ++i) {
                float xv = xs[rt * 8 + i][kk];
                acc[i].x += xv * w.x;
                acc[i].y += xv * w.y;
                acc[i].z += xv * w.z;
                acc[i].w += xv * w.w;
            }
        }
        __syncthreads();
    }

#pragma unroll
    for (int i = 0; i < 8; ++i) {
        int row = row0 + rt * 8 + i;
        if (row < N) {
            H4 h4;
            h4.a = __floats2half2_rn(acc[i].x, acc[i].y);
            h4.b = __floats2half2_rn(acc[i].z, acc[i].w);
            *(H4*)(g_hh + row * HDIM + cg * 4) = h4;
        }
    }
}

// ---------------------------------------------------------------------------
// Head: pooled -> fc1(relu) -> fc2 -> log_softmax. One thread per graph.
// ---------------------------------------------------------------------------
__global__ void head_kernel(const float* __restrict__ fc1w,
                            const float* __restrict__ fc1b,
                            const float* __restrict__ fc2w,
                            const float* __restrict__ fc2b,
                            float* __restrict__ out) {
    int g = threadIdx.x;
    if (g >= N_GRAPHS) return;

    float inv = 1.0f / fmaxf(g_gcnt[g], 1.0f);
    float p[HDIM];
#pragma unroll
    for (int c = 0; c < HDIM; ++c) p[c] = g_gsum[g * HDIM + c] * inv;

    float z1[32];
#pragma unroll
    for (int j = 0; j < 32; ++j) {
        float s = fc1b[j];
#pragma unroll
        for (int c = 0; c < HDIM; ++c) s += p[c] * fc1w[c * 32 + j];
        z1[j] = fmaxf(s, 0.f);
    }

    float z2[10];
    float m = -1e30f;
#pragma unroll
    for (int k = 0; k < 10; ++k) {
        float s = fc2b[k];
#pragma unroll
        for (int j = 0; j < 32; ++j) s += z1[j] * fc2w[j * 10 + k];
        z2[k] = s;
        m = fmaxf(m, s);
    }
    float se = 0.f;
#pragma unroll
    for (int k = 0; k < 10; ++k) se += expf(z2[k] - m);
    float lse = m + logf(se);
#pragma unroll
    for (int k = 0; k < 10; ++k) out[g * 10 + k] = z2[k] - lse;
}

// ---------------------------------------------------------------------------
// Launch — round-10/13 topology (proven): build || gemm1, then serial.
// Streams/events lazily created OUTSIDE capture.
// ---------------------------------------------------------------------------
static cudaStream_t s_side = 0;
static cudaEvent_t  s_ev_fork = 0, s_ev_join = 0;

extern "C" void kernel_launch(void* const* d_in, const int* in_sizes, int n_in,
                              void* d_out, int out_size) {
    const float* x     = (const float*)d_in[0];
    const int*   ei    = (const int*)d_in[1];    // int32
    const int*   batch = (const int*)d_in[2];    // int32
    const float* W1    = (const float*)d_in[3];
    const float* b1    = (const float*)d_in[4];
    const float* W2    = (const float*)d_in[5];
    const float* b2    = (const float*)d_in[6];
    const float* fc1w  = (const float*)d_in[7];
    const float* fc1b  = (const float*)d_in[8];
    const float* fc2w  = (const float*)d_in[9];
    const float* fc2b  = (const float*)d_in[10];
    float* out = (float*)d_out;

    int N = in_sizes[0] / 128;   // nodes
    int E = in_sizes[1] / 2;     // edges

    if (!s_side) {
        cudaStreamCreateWithFlags(&s_side, cudaStreamNonBlocking);
        cudaEventCreateWithFlags(&s_ev_fork, cudaEventDisableTiming);
        cudaEventCreateWithFlags(&s_ev_join, cudaEventDisableTiming);
    }

    int gemm_blocks   = (N + 127) / 128;
    int edge4_blocks  = (E / 4 + 255) / 256 + 1;
    int gather_blocks = (N * 32 + 255) / 256;
    int pool_blocks   = (N + 7) / 8;

    // Fork: CSR build on side stream, concurrent with gemm1 on main stream
    cudaEventRecord(s_ev_fork, 0);
    cudaStreamWaitEvent(s_side, s_ev_fork, 0);

    zero_small_kernel<<<(N + 256) / 256, 256, 0, s_side>>>(N);
    hist_kernel<<<edge4_blocks, 256, 0, s_side>>>(ei, E);
    scan_kernel<<<1, 1024, 0, s_side>>>(N);
    fill_kernel<<<edge4_blocks, 256, 0, s_side>>>(ei, E);
    cudaEventRecord(s_ev_join, s_side);

    // Main stream: gemm1 overlaps the build
    gemm_nodes<128, false><<<gemm_blocks, 256>>>(x, W1, N);

    // Join: gather needs both g_hh and the CSR
    cudaStreamWaitEvent(0, s_ev_join, 0);

    // Layer 1 aggregate: g_agg = relu(gather(g_hh) + b1)
    gather_kernel<<<gather_blocks, 256>>>(b1, N);

    // Layer 2: g_hh = g_agg @ W2 ; pool-fused gather with b2
    gemm_nodes<64, true><<<gemm_blocks, 256>>>(x, W2, N);
    gather_pool_kernel<<<pool_blocks, 256>>>(b2, batch, N);

    // Head
    head_kernel<<<1, 64>>>(fc1w, fc1b, fc2w, fc2b, out);
}

// round 15
// speedup vs baseline: 1.7625x; 1.2312x over previous
#include <cuda_runtime.h>
#include <cuda_fp16.h>
#include <math.h>

#define N_NODES_MAX 50000
#define N_EDGES_MAX 800000
#define HDIM 64
#define N_GRAPHS 64
#define CAP 128          // ELL row capacity (max degree; Poisson(16) -> safe)

// Scratch (device globals — allocation-free; zero-initialized at load).
// Invariant maintained across calls: g_deg, g_gsum, g_gcnt are ZERO at entry
// (consumers re-zero them each call; static init covers the first call).
__device__ __align__(128) __half g_hh[N_NODES_MAX * HDIM];   // 6.4 MB
__device__ __align__(16) float g_agg[N_NODES_MAX * HDIM];    // 12.8 MB
__device__ __align__(16) float g_gsum[N_GRAPHS * HDIM];
__device__ __align__(16) float g_gcnt[N_GRAPHS];
__device__ __align__(16) int g_deg[N_NODES_MAX + 4];
__device__ __align__(16) int g_rank[N_EDGES_MAX + 4];
__device__ __align__(16) int g_col[N_NODES_MAX * CAP];       // 25.6 MB ELL

struct __align__(8) H4 { __half2 a, b; };

// ---------------------------------------------------------------------------
// Packed f32x2 helpers (Blackwell FFMA2 — only reachable via PTX)
// ---------------------------------------------------------------------------
__device__ __forceinline__ unsigned long long pk2(float lo, float hi) {
    unsigned long long r;
    asm("mov.b64 %0, {%1, %2};" : "=l"(r) : "f"(lo), "f"(hi));
    return r;
}
__device__ __forceinline__ unsigned long long pk2s(float v) {
    unsigned long long r;
    asm("mov.b64 %0, {%1, %1};" : "=l"(r) : "f"(v));
    return r;
}
__device__ __forceinline__ void fma2(unsigned long long& d,
                                     unsigned long long a,
                                     unsigned long long b) {
    asm("fma.rn.f32x2 %0, %1, %2, %3;" : "=l"(d) : "l"(a), "l"(b), "l"(d));
}
__device__ __forceinline__ float2 upk2(unsigned long long v) {
    float2 f;
    asm("mov.b64 {%0, %1}, %2;" : "=f"(f.x), "=f"(f.y) : "l"(v));
    return f;
}

// ---------------------------------------------------------------------------
// hist: degree histogram over dst; atomic return value = edge's rank in its
// dst bucket (g_deg was zeroed by the previous call's gather_pool).
// ---------------------------------------------------------------------------
__global__ void hist_kernel(const int* __restrict__ ei, int E) {
    int e = (blockIdx.x * blockDim.x + threadIdx.x) * 4;
    if (e + 3 < E) {
        int4 d = *(const int4*)(ei + E + e);
        int4 r;
        r.x = atomicAdd(&g_deg[d.x], 1);
        r.y = atomicAdd(&g_deg[d.y], 1);
        r.z = atomicAdd(&g_deg[d.z], 1);
        r.w = atomicAdd(&g_deg[d.w], 1);
        *(int4*)(g_rank + e) = r;
    } else {
        for (int j = e; j < E; ++j)
            g_rank[j] = atomicAdd(&g_deg[__ldg(&ei[E + j])], 1);
    }
}

// ---------------------------------------------------------------------------
// fill (ELL): g_col[dst*CAP + rank] = src.  No scan, no dependent loads.
// ---------------------------------------------------------------------------
__global__ void fill_kernel(const int* __restrict__ ei, int E) {
    int e = (blockIdx.x * blockDim.x + threadIdx.x) * 4;
    if (e + 3 < E) {
        int4 s = *(const int4*)(ei + e);
        int4 d = *(const int4*)(ei + E + e);
        int4 r = *(const int4*)(g_rank + e);
        g_col[d.x * CAP + r.x] = s.x;
        g_col[d.y * CAP + r.y] = s.y;
        g_col[d.z * CAP + r.z] = s.z;
        g_col[d.w * CAP + r.w] = s.w;
    } else {
        for (int j = e; j < E; ++j)
            g_col[__ldg(&ei[E + j]) * CAP + g_rank[j]] = __ldg(&ei[j]);
    }
}

// ---------------------------------------------------------------------------
// Warp-cooperative gather from fp16 h (ELL rows).
// Half-warp per edge, uint2 per lane (one 128B line per edge per half-warp),
// fp32 accumulation, 16-edge main batch (8 loads in flight per lane).
// ---------------------------------------------------------------------------
__device__ __forceinline__ void h4_add(float4& acc, uint2 u) {
    __half2 p0 = *(__half2*)&u.x;
    __half2 p1 = *(__half2*)&u.y;
    float2 f0 = __half22float2(p0);
    float2 f1 = __half22float2(p1);
    acc.x += f0.x; acc.y += f0.y; acc.z += f1.x; acc.w += f1.y;
}

__device__ __forceinline__ float4 warp_gather_node(
    int beg, int end, int lane, int half, int hl) {
    const uint2* hp = (const uint2*)g_hh;   // 16 uint2 per row
    float4 acc = {0.f, 0.f, 0.f, 0.f};
    int i = beg;
    while (i < end) {
        int m = min(32, end - i);
        int c = (lane < m) ? __ldg(&g_col[i + lane]) : 0;
        int j = 0;
        for (; j + 16 <= m; j += 16) {
            int s[8];
            uint2 v[8];
#pragma unroll
            for (int q = 0; q < 8; ++q)
                s[q] = __shfl_sync(0xffffffffu, c, j + 2 * q + half);
#pragma unroll
            for (int q = 0; q < 8; ++q)
                v[q] = hp[s[q] * 16 + hl];
#pragma unroll
            for (int q = 0; q < 8; ++q)
                h4_add(acc, v[q]);
        }
        for (; j + 8 <= m; j += 8) {
            int s0 = __shfl_sync(0xffffffffu, c, j     + half);
            int s1 = __shfl_sync(0xffffffffu, c, j + 2 + half);
            int s2 = __shfl_sync(0xffffffffu, c, j + 4 + half);
            int s3 = __shfl_sync(0xffffffffu, c, j + 6 + half);
            uint2 v0 = hp[s0 * 16 + hl];
            uint2 v1 = hp[s1 * 16 + hl];
            uint2 v2 = hp[s2 * 16 + hl];
            uint2 v3 = hp[s3 * 16 + hl];
            h4_add(acc, v0); h4_add(acc, v1);
            h4_add(acc, v2); h4_add(acc, v3);
        }
        for (; j < m; j += 2) {
            int idx = j + half;
            bool valid = idx < m;
            int s = __shfl_sync(0xffffffffu, c, valid ? idx : m - 1);
            uint2 v = hp[s * 16 + hl];
            if (valid) h4_add(acc, v);
        }
        i += m;
    }
    acc.x += __shfl_xor_sync(0xffffffffu, acc.x, 16);
    acc.y += __shfl_xor_sync(0xffffffffu, acc.y, 16);
    acc.z += __shfl_xor_sync(0xffffffffu, acc.z, 16);
    acc.w += __shfl_xor_sync(0xffffffffu, acc.w, 16);
    return acc;
}

// ---------------------------------------------------------------------------
// Layer-1 aggregate: g_agg[n] = relu(gather(g_hh, n) + b1)
// ---------------------------------------------------------------------------
__global__ void __launch_bounds__(256, 8)
gather_kernel(const float* __restrict__ bias, int N) {
    int w = (blockIdx.x * blockDim.x + threadIdx.x) >> 5;
    if (w >= N) return;
    int lane = threadIdx.x & 31;
    int half = lane >> 4;
    int hl   = lane & 15;
    int beg = w * CAP;
    int end = beg + __ldg(&g_deg[w]);

    float4 acc = warp_gather_node(beg, end, lane, half, hl);

    if (half == 0) {
        float4 b = ((const float4*)bias)[hl];
        float4 o;
        o.x = fmaxf(acc.x + b.x, 0.f);
        o.y = fmaxf(acc.y + b.y, 0.f);
        o.z = fmaxf(acc.z + b.z, 0.f);
        o.w = fmaxf(acc.w + b.w, 0.f);
        ((float4*)g_agg)[w * 16 + hl] = o;
    }
}

// ---------------------------------------------------------------------------
// Layer-2 aggregate + mean-pool; LAST consumer of g_deg -> re-zeroes it.
// Sorted batch -> block-level reduction, one atomic set per uniform block.
// ---------------------------------------------------------------------------
__global__ void __launch_bounds__(256, 8)
gather_pool_kernel(const float* __restrict__ b2,
                   const int* __restrict__ batch, int N) {
    __shared__ float4 red[8][16];
    __shared__ int    sg[8];

    int wid  = threadIdx.x >> 5;
    int lane = threadIdx.x & 31;
    int half = lane >> 4;
    int hl   = lane & 15;
    int w = blockIdx.x * 8 + wid;
    bool active = w < N;

    float4 o = {0.f, 0.f, 0.f, 0.f};
    int g = -1;
    if (active) {
        int deg = __ldg(&g_deg[w]);
        int beg = w * CAP;
        float4 acc = warp_gather_node(beg, beg + deg, lane, half, hl);
        if (lane == 0) g_deg[w] = 0;          // recycle for next call's hist
        if (half == 0) {
            float4 b = ((const float4*)b2)[hl];
            o.x = fmaxf(acc.x + b.x, 0.f);
            o.y = fmaxf(acc.y + b.y, 0.f);
            o.z = fmaxf(acc.z + b.z, 0.f);
            o.w = fmaxf(acc.w + b.w, 0.f);
        }
        g = __ldg(&batch[w]);
    }
    if (half == 0) red[wid][hl] = o;
    if (lane == 0) sg[wid] = g;
    __syncthreads();

    int g0 = sg[0];
    bool uniform = (g0 >= 0);
#pragma unroll
    for (int q = 1; q < 8; ++q) uniform = uniform && (sg[q] == g0);

    if (uniform) {
        if (wid == 0 && half == 0) {
            float4 s = red[0][hl];
#pragma unroll
            for (int q = 1; q < 8; ++q) {
                s.x += red[q][hl].x;
                s.y += red[q][hl].y;
                s.z += red[q][hl].z;
                s.w += red[q][hl].w;
            }
            atomicAdd((float4*)(g_gsum + g0 * HDIM + hl * 4), s);
            if (hl == 0) atomicAdd(&g_gcnt[g0], 8.0f);
        }
    } else {
        if (active && half == 0) {
            atomicAdd((float4*)(g_gsum + g * HDIM + hl * 4), o);
            if (hl == 0) atomicAdd(&g_gcnt[g], 1.0f);
        }
    }
}

// ---------------------------------------------------------------------------
// Register-tiled GEMM with packed f32x2 FMA: g_hh[n,64] = src(n,:K) @ W[K,64]
// ---------------------------------------------------------------------------
template <int K, bool SRC_AGG>
__global__ void gemm_nodes(const float* __restrict__ X,
                           const float* __restrict__ Wg,
                           int N) {
    const int KC = 32;
    __shared__ float  xs[128][KC + 1];
    __shared__ float4 ws[KC][16];

    int tid = threadIdx.x;
    int cg  = tid & 15;
    int rt  = tid >> 4;
    int row0 = blockIdx.x * 128;

    unsigned long long acc0[8], acc1[8];   // 8 rows x (2 packed f32x2)
#pragma unroll
    for (int i = 0; i < 8; ++i) { acc0[i] = 0ull; acc1[i] = 0ull; }

    for (int kc = 0; kc < K; kc += KC) {
#pragma unroll
        for (int j = 0; j < 2; ++j) {
            int id = tid + 256 * j;
            int k = id >> 4, c = id & 15;
            ws[k][c] = ((const float4*)Wg)[(kc + k) * 16 + c];
        }
#pragma unroll
        for (int j = 0; j < 4; ++j) {
            int q = tid + 256 * j;
            int r = q >> 3, c4 = q & 7;
            int row = row0 + r;
            float4 v = make_float4(0.f, 0.f, 0.f, 0.f);
            if (row < N) {
                const float* srcp = SRC_AGG ? g_agg : X;
                v = *(const float4*)(srcp + row * K + kc + c4 * 4);
            }
            xs[r][c4 * 4]     = v.x;
            xs[r][c4 * 4 + 1] = v.y;
            xs[r][c4 * 4 + 2] = v.z;
            xs[r][c4 * 4 + 3] = v.w;
        }
        __syncthreads();

#pragma unroll
        for (int kk = 0; kk < KC; ++kk) {
            float4 w = ws[kk][cg];
            unsigned long long wlo = pk2(w.x, w.y);
            unsigned long long whi = pk2(w.z, w.w);
#pragma unroll
            for (int i = 0; i < 8; ++i) {
                unsigned long long xx = pk2s(xs[rt * 8 + i][kk]);
                fma2(acc0[i], xx, wlo);
                fma2(acc1[i], xx, whi);
            }
        }
        __syncthreads();
    }

#pragma unroll
    for (int i = 0; i < 8; ++i) {
        int row = row0 + rt * 8 + i;
        if (row < N) {
            float2 lo = upk2(acc0[i]);
            float2 hi = upk2(acc1[i]);
            H4 h4;
            h4.a = __floats2half2_rn(lo.x, lo.y);
            h4.b = __floats2half2_rn(hi.x, hi.y);
            *(H4*)(g_hh + row * HDIM + cg * 4) = h4;
        }
    }
}

// ---------------------------------------------------------------------------
// Head: pooled -> fc1(relu) -> fc2 -> log_softmax. One thread per graph.
// LAST consumer of g_gsum/g_gcnt -> re-zeroes them for the next call.
// ---------------------------------------------------------------------------
__global__ void head_kernel(const float* __restrict__ fc1w,
                            const float* __restrict__ fc1b,
                            const float* __restrict__ fc2w,
                            const float* __restrict__ fc2b,
                            float* __restrict__ out) {
    int g = threadIdx.x;
    if (g >= N_GRAPHS) return;

    float inv = 1.0f / fmaxf(g_gcnt[g], 1.0f);
    float p[HDIM];
#pragma unroll
    for (int c = 0; c < HDIM; ++c) p[c] = g_gsum[g * HDIM + c] * inv;

    // recycle accumulators for the next call
    g_gcnt[g] = 0.f;
    float4 z4 = {0.f, 0.f, 0.f, 0.f};
#pragma unroll
    for (int c = 0; c < 16; ++c) ((float4*)(g_gsum + g * HDIM))[c] = z4;

    float z1[32];
#pragma unroll
    for (int j = 0; j < 32; ++j) {
        float s = fc1b[j];
#pragma unroll
        for (int c = 0; c < HDIM; ++c) s += p[c] * fc1w[c * 32 + j];
        z1[j] = fmaxf(s, 0.f);
    }

    float z2[10];
    float m = -1e30f;
#pragma unroll
    for (int k = 0; k < 10; ++k) {
        float s = fc2b[k];
#pragma unroll
        for (int j = 0; j < 32; ++j) s += z1[j] * fc2w[j * 10 + k];
        z2[k] = s;
        m = fmaxf(m, s);
    }
    float se = 0.f;
#pragma unroll
    for (int k = 0; k < 10; ++k) se += expf(z2[k] - m);
    float lse = m + logf(se);
#pragma unroll
    for (int k = 0; k < 10; ++k) out[g * 10 + k] = z2[k] - lse;
}

// ---------------------------------------------------------------------------
// Launch — 7 launches.  Side stream: hist -> fill (ELL build, no scan).
// Main stream: gemm1 overlaps the build.  Streams/events created lazily
// OUTSIDE capture (first call is the uncaptured correctness run).
// ---------------------------------------------------------------------------
static cudaStream_t s_side = 0;
static cudaEvent_t  s_ev_fork = 0, s_ev_join = 0;

extern "C" void kernel_launch(void* const* d_in, const int* in_sizes, int n_in,
                              void* d_out, int out_size) {
    const float* x     = (const float*)d_in[0];
    const int*   ei    = (const int*)d_in[1];    // int32
    const int*   batch = (const int*)d_in[2];    // int32
    const float* W1    = (const float*)d_in[3];
    const float* b1    = (const float*)d_in[4];
    const float* W2    = (const float*)d_in[5];
    const float* b2    = (const float*)d_in[6];
    const float* fc1w  = (const float*)d_in[7];
    const float* fc1b  = (const float*)d_in[8];
    const float* fc2w  = (const float*)d_in[9];
    const float* fc2b  = (const float*)d_in[10];
    float* out = (float*)d_out;

    int N = in_sizes[0] / 128;   // nodes
    int E = in_sizes[1] / 2;     // edges

    if (!s_side) {
        cudaStreamCreateWithFlags(&s_side, cudaStreamNonBlocking);
        cudaEventCreateWithFlags(&s_ev_fork, cudaEventDisableTiming);
        cudaEventCreateWithFlags(&s_ev_join, cudaEventDisableTiming);
    }

    int gemm_blocks   = (N + 127) / 128;
    int edge4_blocks  = (E / 4 + 255) / 256 + 1;
    int gather_blocks = (N * 32 + 255) / 256;
    int pool_blocks   = (N + 7) / 8;

    // Fork: ELL build on side stream, concurrent with gemm1 on main stream
    cudaEventRecord(s_ev_fork, 0);
    cudaStreamWaitEvent(s_side, s_ev_fork, 0);

    hist_kernel<<<edge4_blocks, 256, 0, s_side>>>(ei, E);
    fill_kernel<<<edge4_blocks, 256, 0, s_side>>>(ei, E);
    cudaEventRecord(s_ev_join, s_side);

    // Main stream: gemm1 overlaps the build
    gemm_nodes<128, false><<<gemm_blocks, 256>>>(x, W1, N);

    // Join: gather needs both g_hh and the edge lists
    cudaStreamWaitEvent(0, s_ev_join, 0);

    // Layer 1 aggregate: g_agg = relu(gather(g_hh) + b1)
    gather_kernel<<<gather_blocks, 256>>>(b1, N);

    // Layer 2: g_hh = g_agg @ W2 ; pool-fused gather with b2
    gemm_nodes<64, true><<<gemm_blocks, 256>>>(x, W2, N);
    gather_pool_kernel<<<pool_blocks, 256>>>(b2, batch, N);

    // Head (+ accumulator recycle)
    head_kernel<<<1, 64>>>(fc1w, fc1b, fc2w, fc2b, out);
}

// round 16
// speedup vs baseline: 1.7785x; 1.0090x over previous
#include <cuda_runtime.h>
#include <cuda_fp16.h>
#include <math.h>

#define N_NODES_MAX 50000
#define N_EDGES_MAX 800000
#define HDIM 64
#define N_GRAPHS 64
#define CAP 128          // ELL row capacity (max degree; Poisson(16) -> safe)

// Scratch (device globals — allocation-free; zero-initialized at load).
// Invariant maintained across calls: g_deg, g_gsum, g_gcnt are ZERO at entry
// (consumers re-zero them each call; static init covers the first call).
__device__ __align__(128) __half g_hh[N_NODES_MAX * HDIM];   // 6.4 MB
__device__ __align__(16) float g_agg[N_NODES_MAX * HDIM];    // 12.8 MB
__device__ __align__(16) float g_gsum[N_GRAPHS * HDIM];
__device__ __align__(16) float g_gcnt[N_GRAPHS];
__device__ __align__(16) int g_deg[N_NODES_MAX + 4];
__device__ __align__(16) int g_rank[N_EDGES_MAX + 4];
__device__ __align__(16) int g_col[N_NODES_MAX * CAP];       // 25.6 MB ELL

struct __align__(8) H4 { __half2 a, b; };

// ---------------------------------------------------------------------------
// Packed f32x2 helpers (Blackwell FFMA2 — only reachable via PTX)
// ---------------------------------------------------------------------------
__device__ __forceinline__ unsigned long long pk2(float lo, float hi) {
    unsigned long long r;
    asm("mov.b64 %0, {%1, %2};" : "=l"(r) : "f"(lo), "f"(hi));
    return r;
}
__device__ __forceinline__ unsigned long long pk2s(float v) {
    unsigned long long r;
    asm("mov.b64 %0, {%1, %1};" : "=l"(r) : "f"(v));
    return r;
}
__device__ __forceinline__ void fma2(unsigned long long& d,
                                     unsigned long long a,
                                     unsigned long long b) {
    asm("fma.rn.f32x2 %0, %1, %2, %3;" : "=l"(d) : "l"(a), "l"(b), "l"(d));
}
__device__ __forceinline__ float2 upk2(unsigned long long v) {
    float2 f;
    asm("mov.b64 {%0, %1}, %2;" : "=f"(f.x), "=f"(f.y) : "l"(v));
    return f;
}

// ---------------------------------------------------------------------------
// hist: degree histogram over dst; atomic return value = edge's rank in its
// dst bucket (g_deg was zeroed by the previous call's gather_pool).
// ---------------------------------------------------------------------------
__global__ void hist_kernel(const int* __restrict__ ei, int E) {
    int e = (blockIdx.x * blockDim.x + threadIdx.x) * 4;
    if (e + 3 < E) {
        int4 d = *(const int4*)(ei + E + e);
        int4 r;
        r.x = atomicAdd(&g_deg[d.x], 1);
        r.y = atomicAdd(&g_deg[d.y], 1);
        r.z = atomicAdd(&g_deg[d.z], 1);
        r.w = atomicAdd(&g_deg[d.w], 1);
        *(int4*)(g_rank + e) = r;
    } else {
        for (int j = e; j < E; ++j)
            g_rank[j] = atomicAdd(&g_deg[__ldg(&ei[E + j])], 1);
    }
}

// ---------------------------------------------------------------------------
// fill (ELL): g_col[dst*CAP + rank] = src.  No scan, no dependent loads.
// ---------------------------------------------------------------------------
__global__ void fill_kernel(const int* __restrict__ ei, int E) {
    int e = (blockIdx.x * blockDim.x + threadIdx.x) * 4;
    if (e + 3 < E) {
        int4 s = *(const int4*)(ei + e);
        int4 d = *(const int4*)(ei + E + e);
        int4 r = *(const int4*)(g_rank + e);
        g_col[d.x * CAP + r.x] = s.x;
        g_col[d.y * CAP + r.y] = s.y;
        g_col[d.z * CAP + r.z] = s.z;
        g_col[d.w * CAP + r.w] = s.w;
    } else {
        for (int j = e; j < E; ++j)
            g_col[__ldg(&ei[E + j]) * CAP + g_rank[j]] = __ldg(&ei[j]);
    }
}

// ---------------------------------------------------------------------------
// fp16 pair-add on packed uint2 (2 x HADD2) + fp32 finalize
// ---------------------------------------------------------------------------
__device__ __forceinline__ uint2 h2add(uint2 a, uint2 b) {
    __half2 ax = *(__half2*)&a.x, ay = *(__half2*)&a.y;
    __half2 bx = *(__half2*)&b.x, by = *(__half2*)&b.y;
    __half2 rx = __hadd2(ax, bx);
    __half2 ry = __hadd2(ay, by);
    uint2 r;
    r.x = *(unsigned*)&rx;
    r.y = *(unsigned*)&ry;
    return r;
}
__device__ __forceinline__ void h4_add(float4& acc, uint2 u) {
    __half2 p0 = *(__half2*)&u.x;
    __half2 p1 = *(__half2*)&u.y;
    float2 f0 = __half22float2(p0);
    float2 f1 = __half22float2(p1);
    acc.x += f0.x; acc.y += f0.y; acc.z += f1.x; acc.w += f1.y;
}

// ---------------------------------------------------------------------------
// Warp-cooperative gather from fp16 h (ELL rows).
// Half-warp per edge, uint2 per lane (one 128B line per edge per half-warp).
// 16-edge batches are summed with a 3-level HADD2 tree (14 HADD2 + one fp32
// finalize instead of 64 cvt/add) — gather is issue-bound, not BW-bound.
// ---------------------------------------------------------------------------
__device__ __forceinline__ float4 warp_gather_node(
    int beg, int end, int lane, int half, int hl) {
    const uint2* hp = (const uint2*)g_hh;   // 16 uint2 per row
    float4 acc = {0.f, 0.f, 0.f, 0.f};
    int i = beg;
    while (i < end) {
        int m = min(32, end - i);
        int c = (lane < m) ? __ldg(&g_col[i + lane]) : 0;
        int j = 0;
        for (; j + 16 <= m; j += 16) {
            int s[8];
            uint2 v[8];
#pragma unroll
            for (int q = 0; q < 8; ++q)
                s[q] = __shfl_sync(0xffffffffu, c, j + 2 * q + half);
#pragma unroll
            for (int q = 0; q < 8; ++q)
                v[q] = hp[s[q] * 16 + hl];
            // 3-level fp16 tree, one fp32 finalize
            uint2 t01 = h2add(v[0], v[1]);
            uint2 t23 = h2add(v[2], v[3]);
            uint2 t45 = h2add(v[4], v[5]);
            uint2 t67 = h2add(v[6], v[7]);
            uint2 t03 = h2add(t01, t23);
            uint2 t47 = h2add(t45, t67);
            h4_add(acc, h2add(t03, t47));
        }
        for (; j + 8 <= m; j += 8) {
            int s0 = __shfl_sync(0xffffffffu, c, j     + half);
            int s1 = __shfl_sync(0xffffffffu, c, j + 2 + half);
            int s2 = __shfl_sync(0xffffffffu, c, j + 4 + half);
            int s3 = __shfl_sync(0xffffffffu, c, j + 6 + half);
            uint2 v0 = hp[s0 * 16 + hl];
            uint2 v1 = hp[s1 * 16 + hl];
            uint2 v2 = hp[s2 * 16 + hl];
            uint2 v3 = hp[s3 * 16 + hl];
            // 2-level fp16 tree
            h4_add(acc, h2add(h2add(v0, v1), h2add(v2, v3)));
        }
        for (; j < m; j += 2) {
            int idx = j + half;
            bool valid = idx < m;
            int s = __shfl_sync(0xffffffffu, c, valid ? idx : m - 1);
            uint2 v = hp[s * 16 + hl];
            if (valid) h4_add(acc, v);
        }
        i += m;
    }
    acc.x += __shfl_xor_sync(0xffffffffu, acc.x, 16);
    acc.y += __shfl_xor_sync(0xffffffffu, acc.y, 16);
    acc.z += __shfl_xor_sync(0xffffffffu, acc.z, 16);
    acc.w += __shfl_xor_sync(0xffffffffu, acc.w, 16);
    return acc;
}

// ---------------------------------------------------------------------------
// Layer-1 aggregate: g_agg[n] = relu(gather(g_hh, n) + b1)
// ---------------------------------------------------------------------------
__global__ void __launch_bounds__(256, 8)
gather_kernel(const float* __restrict__ bias, int N) {
    int w = (blockIdx.x * blockDim.x + threadIdx.x) >> 5;
    if (w >= N) return;
    int lane = threadIdx.x & 31;
    int half = lane >> 4;
    int hl   = lane & 15;
    int beg = w * CAP;
    int end = beg + __ldg(&g_deg[w]);

    float4 acc = warp_gather_node(beg, end, lane, half, hl);

    if (half == 0) {
        float4 b = ((const float4*)bias)[hl];
        float4 o;
        o.x = fmaxf(acc.x + b.x, 0.f);
        o.y = fmaxf(acc.y + b.y, 0.f);
        o.z = fmaxf(acc.z + b.z, 0.f);
        o.w = fmaxf(acc.w + b.w, 0.f);
        ((float4*)g_agg)[w * 16 + hl] = o;
    }
}

// ---------------------------------------------------------------------------
// Layer-2 aggregate + mean-pool; LAST consumer of g_deg -> re-zeroes it.
// Sorted batch -> block-level reduction, one atomic set per uniform block.
// ---------------------------------------------------------------------------
__global__ void __launch_bounds__(256, 8)
gather_pool_kernel(const float* __restrict__ b2,
                   const int* __restrict__ batch, int N) {
    __shared__ float4 red[8][16];
    __shared__ int    sg[8];

    int wid  = threadIdx.x >> 5;
    int lane = threadIdx.x & 31;
    int half = lane >> 4;
    int hl   = lane & 15;
    int w = blockIdx.x * 8 + wid;
    bool active = w < N;

    float4 o = {0.f, 0.f, 0.f, 0.f};
    int g = -1;
    if (active) {
        int deg = __ldg(&g_deg[w]);
        int beg = w * CAP;
        float4 acc = warp_gather_node(beg, beg + deg, lane, half, hl);
        if (lane == 0) g_deg[w] = 0;          // recycle for next call's hist
        if (half == 0) {
            float4 b = ((const float4*)b2)[hl];
            o.x = fmaxf(acc.x + b.x, 0.f);
            o.y = fmaxf(acc.y + b.y, 0.f);
            o.z = fmaxf(acc.z + b.z, 0.f);
            o.w = fmaxf(acc.w + b.w, 0.f);
        }
        g = __ldg(&batch[w]);
    }
    if (half == 0) red[wid][hl] = o;
    if (lane == 0) sg[wid] = g;
    __syncthreads();

    int g0 = sg[0];
    bool uniform = (g0 >= 0);
#pragma unroll
    for (int q = 1; q < 8; ++q) uniform = uniform && (sg[q] == g0);

    if (uniform) {
        if (wid == 0 && half == 0) {
            float4 s = red[0][hl];
#pragma unroll
            for (int q = 1; q < 8; ++q) {
                s.x += red[q][hl].x;
                s.y += red[q][hl].y;
                s.z += red[q][hl].z;
                s.w += red[q][hl].w;
            }
            atomicAdd((float4*)(g_gsum + g0 * HDIM + hl * 4), s);
            if (hl == 0) atomicAdd(&g_gcnt[g0], 8.0f);
        }
    } else {
        if (active && half == 0) {
            atomicAdd((float4*)(g_gsum + g * HDIM + hl * 4), o);
            if (hl == 0) atomicAdd(&g_gcnt[g], 1.0f);
        }
    }
}

// ---------------------------------------------------------------------------
// Register-tiled GEMM with packed f32x2 FMA: g_hh[n,64] = src(n,:K) @ W[K,64]
// ---------------------------------------------------------------------------
template <int K, bool SRC_AGG>
__global__ void gemm_nodes(const float* __restrict__ X,
                           const float* __restrict__ Wg,
                           int N) {
    const int KC = 32;
    __shared__ float  xs[128][KC + 1];
    __shared__ float4 ws[KC][16];

    int tid = threadIdx.x;
    int cg  = tid & 15;
    int rt  = tid >> 4;
    int row0 = blockIdx.x * 128;

    unsigned long long acc0[8], acc1[8];   // 8 rows x (2 packed f32x2)
#pragma unroll
    for (int i = 0; i < 8; ++i) { acc0[i] = 0ull; acc1[i] = 0ull; }

    for (int kc = 0; kc < K; kc += KC) {
#pragma unroll
        for (int j = 0; j < 2; ++j) {
            int id = tid + 256 * j;
            int k = id >> 4, c = id & 15;
            ws[k][c] = ((const float4*)Wg)[(kc + k) * 16 + c];
        }
#pragma unroll
        for (int j = 0; j < 4; ++j) {
            int q = tid + 256 * j;
            int r = q >> 3, c4 = q & 7;
            int row = row0 + r;
            float4 v = make_float4(0.f, 0.f, 0.f, 0.f);
            if (row < N) {
                const float* srcp = SRC_AGG ? g_agg : X;
                v = *(const float4*)(srcp + row * K + kc + c4 * 4);
            }
            xs[r][c4 * 4]     = v.x;
            xs[r][c4 * 4 + 1] = v.y;
            xs[r][c4 * 4 + 2] = v.z;
            xs[r][c4 * 4 + 3] = v.w;
        }
        __syncthreads();

#pragma unroll
        for (int kk = 0; kk < KC; ++kk) {
            float4 w = ws[kk][cg];
            unsigned long long wlo = pk2(w.x, w.y);
            unsigned long long whi = pk2(w.z, w.w);
#pragma unroll
            for (int i = 0; i < 8; ++i) {
                unsigned long long xx = pk2s(xs[rt * 8 + i][kk]);
                fma2(acc0[i], xx, wlo);
                fma2(acc1[i], xx, whi);
            }
        }
        __syncthreads();
    }

#pragma unroll
    for (int i = 0; i < 8; ++i) {
        int row = row0 + rt * 8 + i;
        if (row < N) {
            float2 lo = upk2(acc0[i]);
            float2 hi = upk2(acc1[i]);
            H4 h4;
            h4.a = __floats2half2_rn(lo.x, lo.y);
            h4.b = __floats2half2_rn(hi.x, hi.y);
            *(H4*)(g_hh + row * HDIM + cg * 4) = h4;
        }
    }
}

// ---------------------------------------------------------------------------
// Head: pooled -> fc1(relu) -> fc2 -> log_softmax. One thread per graph.
// LAST consumer of g_gsum/g_gcnt -> re-zeroes them for the next call.
// ---------------------------------------------------------------------------
__global__ void head_kernel(const float* __restrict__ fc1w,
                            const float* __restrict__ fc1b,
                            const float* __restrict__ fc2w,
                            const float* __restrict__ fc2b,
                            float* __restrict__ out) {
    int g = threadIdx.x;
    if (g >= N_GRAPHS) return;

    float inv = 1.0f / fmaxf(g_gcnt[g], 1.0f);
    float p[HDIM];
#pragma unroll
    for (int c = 0; c < HDIM; ++c) p[c] = g_gsum[g * HDIM + c] * inv;

    // recycle accumulators for the next call
    g_gcnt[g] = 0.f;
    float4 z4 = {0.f, 0.f, 0.f, 0.f};
#pragma unroll
    for (int c = 0; c < 16; ++c) ((float4*)(g_gsum + g * HDIM))[c] = z4;

    float z1[32];
#pragma unroll
    for (int j = 0; j < 32; ++j) {
        float s = fc1b[j];
#pragma unroll
        for (int c = 0; c < HDIM; ++c) s += p[c] * fc1w[c * 32 + j];
        z1[j] = fmaxf(s, 0.f);
    }

    float z2[10];
    float m = -1e30f;
#pragma unroll
    for (int k = 0; k < 10; ++k) {
        float s = fc2b[k];
#pragma unroll
        for (int j = 0; j < 32; ++j) s += z1[j] * fc2w[j * 10 + k];
        z2[k] = s;
        m = fmaxf(m, s);
    }
    float se = 0.f;
#pragma unroll
    for (int k = 0; k < 10; ++k) se += expf(z2[k] - m);
    float lse = m + logf(se);
#pragma unroll
    for (int k = 0; k < 10; ++k) out[g * 10 + k] = z2[k] - lse;
}

// ---------------------------------------------------------------------------
// Launch — 7 launches.  Side stream: hist -> fill (ELL build, no scan).
// Main stream: gemm1 overlaps the build.  Streams/events created lazily
// OUTSIDE capture (first call is the uncaptured correctness run).
// ---------------------------------------------------------------------------
static cudaStream_t s_side = 0;
static cudaEvent_t  s_ev_fork = 0, s_ev_join = 0;

extern "C" void kernel_launch(void* const* d_in, const int* in_sizes, int n_in,
                              void* d_out, int out_size) {
    const float* x     = (const float*)d_in[0];
    const int*   ei    = (const int*)d_in[1];    // int32
    const int*   batch = (const int*)d_in[2];    // int32
    const float* W1    = (const float*)d_in[3];
    const float* b1    = (const float*)d_in[4];
    const float* W2    = (const float*)d_in[5];
    const float* b2    = (const float*)d_in[6];
    const float* fc1w  = (const float*)d_in[7];
    const float* fc1b  = (const float*)d_in[8];
    const float* fc2w  = (const float*)d_in[9];
    const float* fc2b  = (const float*)d_in[10];
    float* out = (float*)d_out;

    int N = in_sizes[0] / 128;   // nodes
    int E = in_sizes[1] / 2;     // edges

    if (!s_side) {
        cudaStreamCreateWithFlags(&s_side, cudaStreamNonBlocking);
        cudaEventCreateWithFlags(&s_ev_fork, cudaEventDisableTiming);
        cudaEventCreateWithFlags(&s_ev_join, cudaEventDisableTiming);
    }

    int gemm_blocks   = (N + 127) / 128;
    int edge4_blocks  = (E / 4 + 255) / 256 + 1;
    int gather_blocks = (N * 32 + 255) / 256;
    int pool_blocks   = (N + 7) / 8;

    // Fork: ELL build on side stream, concurrent with gemm1 on main stream
    cudaEventRecord(s_ev_fork, 0);
    cudaStreamWaitEvent(s_side, s_ev_fork, 0);

    hist_kernel<<<edge4_blocks, 256, 0, s_side>>>(ei, E);
    fill_kernel<<<edge4_blocks, 256, 0, s_side>>>(ei, E);
    cudaEventRecord(s_ev_join, s_side);

    // Main stream: gemm1 overlaps the build
    gemm_nodes<128, false><<<gemm_blocks, 256>>>(x, W1, N);

    // Join: gather needs both g_hh and the edge lists
    cudaStreamWaitEvent(0, s_ev_join, 0);

    // Layer 1 aggregate: g_agg = relu(gather(g_hh) + b1)
    gather_kernel<<<gather_blocks, 256>>>(b1, N);

    // Layer 2: g_hh = g_agg @ W2 ; pool-fused gather with b2
    gemm_nodes<64, true><<<gemm_blocks, 256>>>(x, W2, N);
    gather_pool_kernel<<<pool_blocks, 256>>>(b2, batch, N);

    // Head (+ accumulator recycle)
    head_kernel<<<1, 64>>>(fc1w, fc1b, fc2w, fc2b, out);
}